// round 4
// baseline (speedup 1.0000x reference)
#include <cuda_runtime.h>

// 2-layer GCN via per-call CSR build + pull aggregation (no feature atomics).
// out_d = dv_d * sum_{s in N(d) ∪ {d}} (h_s * dv_s) + b,  dv = rsqrt(deg), deg = indeg+1.

#define NMAX 200000
#define EMAX 6400000
#define SCAN_B 1024

__device__ int   g_cnt [NMAX];        // in-degree histogram
__device__ int   g_off [NMAX];        // CSR offsets (exclusive scan of cnt)
__device__ int   g_cur [NMAX];        // placement cursors
__device__ int   g_bsum[256];
__device__ int   g_boff[256];
__device__ int   g_ssrc[EMAX];        // src ids grouped by dst
__device__ float g_dinv[NMAX];
__device__ float g_hs1 [NMAX * 16];   // (x@W1)*dinv
__device__ float g_v   [NMAX * 16];   // relu(layer1 out)
__device__ float g_hs2p[NMAX * 4];    // (v@W2)*dinv, padded to 4

__global__ void k_zero_cnt(int n) {
    int i = blockIdx.x * blockDim.x + threadIdx.x;
    if (i < n) g_cnt[i] = 0;
}

__global__ void k_hist(const int* __restrict__ dst, int E) {
    int e = blockIdx.x * blockDim.x + threadIdx.x;
    if (e < E) atomicAdd(&g_cnt[dst[e]], 1);
}

// block-level exclusive scan (Hillis-Steele in smem)
__global__ void k_scan_block(int n) {
    __shared__ int sh[SCAN_B];
    int i = blockIdx.x * SCAN_B + threadIdx.x;
    int v = (i < n) ? g_cnt[i] : 0;
    sh[threadIdx.x] = v;
    __syncthreads();
#pragma unroll
    for (int off = 1; off < SCAN_B; off <<= 1) {
        int t = (threadIdx.x >= off) ? sh[threadIdx.x - off] : 0;
        __syncthreads();
        sh[threadIdx.x] += t;
        __syncthreads();
    }
    if (i < n) g_off[i] = sh[threadIdx.x] - v;           // exclusive
    if (threadIdx.x == SCAN_B - 1) g_bsum[blockIdx.x] = sh[threadIdx.x];
}

__global__ void k_scan_bsum(int nb) {
    __shared__ int sh[256];
    int i = threadIdx.x;
    int v = (i < nb) ? g_bsum[i] : 0;
    sh[i] = v;
    __syncthreads();
#pragma unroll
    for (int off = 1; off < 256; off <<= 1) {
        int t = (i >= off) ? sh[i - off] : 0;
        __syncthreads();
        sh[i] += t;
        __syncthreads();
    }
    if (i < nb) g_boff[i] = sh[i] - v;                   // exclusive
}

// finalize offsets+cursors, dinv, hs1 = (x@W1)*dinv  (one pass over nodes)
__global__ void k_node_prep(const float* __restrict__ x,
                            const float* __restrict__ W1, int n) {
    int i = blockIdx.x * blockDim.x + threadIdx.x;
    if (i >= n) return;
    int off = g_off[i] + g_boff[i / SCAN_B];
    g_off[i] = off;
    g_cur[i] = off;
    float dv = rsqrtf((float)g_cnt[i] + 1.0f);
    g_dinv[i] = dv;
    float x0 = x[i * 3 + 0], x1 = x[i * 3 + 1], x2 = x[i * 3 + 2];
#pragma unroll
    for (int f = 0; f < 16; f++) {
        float h = x0 * __ldg(&W1[f]) + x1 * __ldg(&W1[16 + f]) + x2 * __ldg(&W1[32 + f]);
        g_hs1[i * 16 + f] = h * dv;
    }
}

__global__ void k_place(const int* __restrict__ src,
                        const int* __restrict__ dst, int E) {
    int e = blockIdx.x * blockDim.x + threadIdx.x;
    if (e >= E) return;
    int d = dst[e];
    int pos = atomicAdd(&g_cur[d], 1);
    g_ssrc[pos] = src[e];
}

// layer-1 pull aggregation: 16 lanes per node; neighbor ids chunk-loaded +
// shuffle-broadcast; gather of hs1 row is one coalesced 64B region per neighbor.
__global__ void k_agg1(const float* __restrict__ b1, int n) {
    int t = blockIdx.x * blockDim.x + threadIdx.x;
    int node = t >> 4;
    int f = t & 15;
    bool valid = node < n;
    unsigned gmask = 0xFFFFu << (threadIdx.x & 16);

    int beg = 0, ct = 0;
    float acc = 0.0f;
    if (valid) {
        beg = g_off[node];
        ct  = g_cnt[node];
        acc = g_hs1[(long long)node * 16 + f];   // self loop
    }
    for (int base = 0; base < ct; base += 16) {
        int m = ct - base; if (m > 16) m = 16;
        int sid = (f < m) ? g_ssrc[beg + base + f] : 0;
#pragma unroll 4
        for (int j = 0; j < m; j++) {
            int s = __shfl_sync(gmask, sid, j, 16);
            acc += g_hs1[(long long)s * 16 + f];
        }
    }
    if (valid) {
        float v = fmaxf(acc * g_dinv[node] + __ldg(&b1[f]), 0.0f);
        g_v[(long long)node * 16 + f] = v;
    }
}

// hs2 = (v@W2)*dinv, padded to 4 floats per node (lane 3 = 0)
__global__ void k_layer2_node(const float* __restrict__ W2, int n) {
    int i = blockIdx.x * blockDim.x + threadIdx.x;
    if (i >= n) return;
    float dv = g_dinv[i];
    float v[16];
#pragma unroll
    for (int f = 0; f < 16; f++) v[f] = g_v[(long long)i * 16 + f];
    float4 r;
    float h0 = 0, h1 = 0, h2 = 0;
#pragma unroll
    for (int f = 0; f < 16; f++) {
        h0 += v[f] * __ldg(&W2[f * 3 + 0]);
        h1 += v[f] * __ldg(&W2[f * 3 + 1]);
        h2 += v[f] * __ldg(&W2[f * 3 + 2]);
    }
    r.x = h0 * dv; r.y = h1 * dv; r.z = h2 * dv; r.w = 0.0f;
    *reinterpret_cast<float4*>(&g_hs2p[(long long)i * 4]) = r;
}

// layer-2 pull aggregation: 4 lanes per node (lane 3 pad)
__global__ void k_agg2(const float* __restrict__ b2,
                       float* __restrict__ out, int n) {
    int t = blockIdx.x * blockDim.x + threadIdx.x;
    int node = t >> 2;
    int c = t & 3;
    bool valid = node < n;
    unsigned gmask = 0xFu << (threadIdx.x & 28);

    int beg = 0, ct = 0;
    float acc = 0.0f;
    if (valid) {
        beg = g_off[node];
        ct  = g_cnt[node];
        acc = g_hs2p[(long long)node * 4 + c];   // self loop
    }
    for (int base = 0; base < ct; base += 4) {
        int m = ct - base; if (m > 4) m = 4;
        int sid = (c < m) ? g_ssrc[beg + base + c] : 0;
#pragma unroll 4
        for (int j = 0; j < m; j++) {
            int s = __shfl_sync(gmask, sid, j, 4);
            acc += g_hs2p[(long long)s * 4 + c];
        }
    }
    if (valid && c < 3)
        out[(long long)node * 3 + c] = acc * g_dinv[node] + __ldg(&b2[c]);
}

extern "C" void kernel_launch(void* const* d_in, const int* in_sizes, int n_in,
                              void* d_out, int out_size) {
    const float* x  = (const float*)d_in[0];
    const int*   ei = (const int*)  d_in[1];
    const float* W1 = (const float*)d_in[2];
    const float* b1 = (const float*)d_in[3];
    const float* W2 = (const float*)d_in[4];
    const float* b2 = (const float*)d_in[5];
    float* out = (float*)d_out;

    int n = in_sizes[0] / 3;
    int E = in_sizes[1] / 2;
    const int* src = ei;
    const int* dst = ei + E;

    const int B = 256;
    int gn = (n + B - 1) / B;
    int nb = (n + SCAN_B - 1) / SCAN_B;

    k_zero_cnt<<<gn, B>>>(n);
    k_hist<<<(E + B - 1) / B, B>>>(dst, E);
    k_scan_block<<<nb, SCAN_B>>>(n);
    k_scan_bsum<<<1, 256>>>(nb);
    k_node_prep<<<gn, B>>>(x, W1, n);
    k_place<<<(E + B - 1) / B, B>>>(src, dst, E);
    {
        long long tot = (long long)n * 16;
        k_agg1<<<(int)((tot + B - 1) / B), B>>>(b1, n);
    }
    k_layer2_node<<<gn, B>>>(W2, n);
    {
        long long tot = (long long)n * 4;
        k_agg2<<<(int)((tot + B - 1) / B), B>>>(b2, out, n);
    }
}

// round 5
// speedup vs baseline: 1.8502x; 1.8502x over previous
#include <cuda_runtime.h>

// 2-layer GCN, scatter form, with "project-on-the-small-side" trick:
//   layer1: aggregate xs = x*dinv (3-dim, padded to 4) over edges, THEN apply W1.
//   layer2: project m = (v@W2)*dinv (3-dim, padded to 4), THEN aggregate.
// Self loops handled by initializing acc = own message.

#define NMAX 200000

__device__ int   g_cnt [NMAX];
__device__ float g_dinv[NMAX];
__device__ float4 g_xs  [NMAX];   // x*dinv padded
__device__ float4 g_acc1[NMAX];   // layer1 aggregate
__device__ float4 g_m2  [NMAX];   // (v@W2)*dinv padded
__device__ float4 g_acc2[NMAX];   // layer2 aggregate

__global__ void k_zero_cnt(int n) {
    int i = blockIdx.x * blockDim.x + threadIdx.x;
    if (i < n) g_cnt[i] = 0;
}

__global__ void k_hist(const int* __restrict__ dst, int E) {
    int e = blockIdx.x * blockDim.x + threadIdx.x;
    if (e < E) atomicAdd(&g_cnt[dst[e]], 1);
}

// dinv, xs = x*dinv (pad 0), acc1 = xs (self loop)
__global__ void k_prep1(const float* __restrict__ x, int n) {
    int i = blockIdx.x * blockDim.x + threadIdx.x;
    if (i >= n) return;
    float dv = rsqrtf((float)g_cnt[i] + 1.0f);
    g_dinv[i] = dv;
    float4 v;
    v.x = x[i * 3 + 0] * dv;
    v.y = x[i * 3 + 1] * dv;
    v.z = x[i * 3 + 2] * dv;
    v.w = 0.0f;
    g_xs[i]   = v;
    g_acc1[i] = v;
}

// 1 thread/edge: 16B gather + 16B vector reduction
__global__ void k_scatter1(const int* __restrict__ src,
                           const int* __restrict__ dst, int E) {
    int e = blockIdx.x * blockDim.x + threadIdx.x;
    if (e >= E) return;
    int s = src[e], d = dst[e];
    float4 v = g_xs[s];
    float* p = (float*)&g_acc1[d];
    asm volatile("red.global.add.v4.f32 [%0], {%1, %2, %3, %4};"
                 :: "l"(p), "f"(v.x), "f"(v.y), "f"(v.z), "f"(v.w)
                 : "memory");
}

// v = relu(dv*(acc1@W1)+b1);  m2 = (v@W2)*dv;  acc2 = m2 (self loop)
__global__ void k_prep2(const float* __restrict__ W1,
                        const float* __restrict__ b1,
                        const float* __restrict__ W2, int n) {
    int i = blockIdx.x * blockDim.x + threadIdx.x;
    if (i >= n) return;
    float dv = g_dinv[i];
    float4 a = g_acc1[i];
    float h0 = 0.0f, h1 = 0.0f, h2 = 0.0f;
#pragma unroll
    for (int f = 0; f < 16; f++) {
        float h = a.x * __ldg(&W1[f]) + a.y * __ldg(&W1[16 + f]) + a.z * __ldg(&W1[32 + f]);
        float v = fmaxf(h * dv + __ldg(&b1[f]), 0.0f);
        h0 += v * __ldg(&W2[f * 3 + 0]);
        h1 += v * __ldg(&W2[f * 3 + 1]);
        h2 += v * __ldg(&W2[f * 3 + 2]);
    }
    float4 m;
    m.x = h0 * dv; m.y = h1 * dv; m.z = h2 * dv; m.w = 0.0f;
    g_m2[i]   = m;
    g_acc2[i] = m;
}

__global__ void k_scatter2(const int* __restrict__ src,
                           const int* __restrict__ dst, int E) {
    int e = blockIdx.x * blockDim.x + threadIdx.x;
    if (e >= E) return;
    int s = src[e], d = dst[e];
    float4 v = g_m2[s];
    float* p = (float*)&g_acc2[d];
    asm volatile("red.global.add.v4.f32 [%0], {%1, %2, %3, %4};"
                 :: "l"(p), "f"(v.x), "f"(v.y), "f"(v.z), "f"(v.w)
                 : "memory");
}

__global__ void k_final(const float* __restrict__ b2,
                        float* __restrict__ out, int n) {
    int i = blockIdx.x * blockDim.x + threadIdx.x;
    if (i >= n) return;
    float dv = g_dinv[i];
    float4 a = g_acc2[i];
    out[i * 3 + 0] = a.x * dv + __ldg(&b2[0]);
    out[i * 3 + 1] = a.y * dv + __ldg(&b2[1]);
    out[i * 3 + 2] = a.z * dv + __ldg(&b2[2]);
}

extern "C" void kernel_launch(void* const* d_in, const int* in_sizes, int n_in,
                              void* d_out, int out_size) {
    const float* x  = (const float*)d_in[0];
    const int*   ei = (const int*)  d_in[1];
    const float* W1 = (const float*)d_in[2];
    const float* b1 = (const float*)d_in[3];
    const float* W2 = (const float*)d_in[4];
    const float* b2 = (const float*)d_in[5];
    float* out = (float*)d_out;

    int n = in_sizes[0] / 3;
    int E = in_sizes[1] / 2;
    const int* src = ei;
    const int* dst = ei + E;

    const int B = 256;
    int gn = (n + B - 1) / B;
    int ge = (E + B - 1) / B;

    k_zero_cnt<<<gn, B>>>(n);
    k_hist<<<ge, B>>>(dst, E);
    k_prep1<<<gn, B>>>(x, n);
    k_scatter1<<<ge, B>>>(src, dst, E);
    k_prep2<<<gn, B>>>(W1, b1, W2, n);
    k_scatter2<<<ge, B>>>(src, dst, E);
    k_final<<<gn, B>>>(b2, out, n);
}